// round 5
// baseline (speedup 1.0000x reference)
#include <cuda_runtime.h>
#include <cstdint>

#define NBATCH 4
#define HEADS  16
#define QL     2048
#define KVL    2048
#define HD     64
#define ED     1024
#define K2E    0.045084220027780106f   /* (1/sqrt(1024)) * log2(e) */

#define BQ 128
#define BN 64
#define NCHUNK (KVL / BN)

/* scratch: attention output [N, Q, E] fp32 (32 MB) + bit-packed mask (2 MB) */
static __device__ float    g_attn[NBATCH * QL * ED];
static __device__ uint32_t g_maskbits[NBATCH * QL * (KVL / 32)];

/* smem word offsets */
#define OFF_QS 0        /* Q fragments:  8 warps x 1024 words  */
#define OFF_KS 8192     /* K fragments:  8 tiles x 512 words   */
#define OFF_VS 12288    /* V fragments:  8 tiles x 512 words   */
#define OFF_PS 16384    /* P fragments:  8 warps x 1088 words  */
#define SMEM_WORDS 25088
#define SMEM_BYTES (SMEM_WORDS * 4)

/* ----------------------------- small helpers ----------------------------- */
__device__ __forceinline__ uint32_t f2t(float x) {          /* f32 -> tf32 bits */
    uint32_t u;
    asm("cvt.rna.tf32.f32 %0, %1;" : "=r"(u) : "f"(x));
    return u;
}
__device__ __forceinline__ float ex2f(float x) {
    float r;
    asm("ex2.approx.f32 %0, %1;" : "=f"(r) : "f"(x));
    return r;
}

/* D(16x8,f32) += A(16x8,tf32) * B(8x8,tf32)  —  m16n8k8 row.col */
__device__ __forceinline__ void mma8(float* d, const uint32_t* a,
                                     uint32_t b0, uint32_t b1) {
    asm volatile(
        "mma.sync.aligned.m16n8k8.row.col.f32.tf32.tf32.f32 "
        "{%0,%1,%2,%3}, {%4,%5,%6,%7}, {%8,%9}, {%0,%1,%2,%3};"
        : "+f"(d[0]), "+f"(d[1]), "+f"(d[2]), "+f"(d[3])
        : "r"(a[0]), "r"(a[1]), "r"(a[2]), "r"(a[3]), "r"(b0), "r"(b1));
}

/* --------------------------- mask bit-packing ---------------------------- */
__global__ void maskpack(const int* __restrict__ M) {
    int warpid = (blockIdx.x * blockDim.x + threadIdx.x) >> 5;
    int lane = threadIdx.x & 31;
    size_t base = (size_t)warpid * 8;
    #pragma unroll
    for (int t = 0; t < 8; t++) {
        size_t wd = base + t;
        int v = M[wd * 32 + lane];
        uint32_t bits = __ballot_sync(0xffffffffu, v != 0);
        if (lane == 0) g_maskbits[wd] = bits;
    }
}

/* -------------------- tf32 mma.sync flash attention ---------------------- */
/* 8 warps; warp w owns q-rows [w*16, w*16+16). lane: g=lane>>2, c=lane&3.
   Fragment-order smem layouts (see addr formulas inline); all B-frag reads
   are LDS.128, P A-frag reads LDS.64, conflict-free via XOR / pitch swizzle. */
__global__ __launch_bounds__(256, 2)
void attn_mma(const float* __restrict__ Q, const float* __restrict__ K,
              const float* __restrict__ V)
{
    extern __shared__ uint32_t sm[];
    uint32_t* QS = sm + OFF_QS;
    uint32_t* KS = sm + OFF_KS;
    uint32_t* VS = sm + OFF_VS;
    uint32_t* PS = sm + OFF_PS;

    const int tid = threadIdx.x, w = tid >> 5, lane = tid & 31;
    const int g = lane >> 2, c = lane & 3;
    const int Lme = g * 4 + c;
    const int xL  = (Lme >> 1) & 3;
    const int n = blockIdx.y >> 4, h = blockIdx.y & 15;
    const int q0 = blockIdx.x * BQ;

    const float* qb = Q + ((size_t)n * QL + q0) * ED + h * HD;
    const float* kb = K + (size_t)n * KVL * ED + h * HD;
    const float* vb = V + (size_t)n * KVL * ED + h * HD;

    /* ---- stage Q fragments: addr = w*1024 + L*32 + ((ks^ (L&7))<<2) + reg */
    #pragma unroll
    for (int j = 0; j < 8; j++) {
        int flat = tid + 256 * j;
        int r = flat >> 4, d0 = (flat & 15) * 4;
        float4 qv = *(const float4*)(qb + (size_t)r * ED + d0);
        int wt = r >> 4, gg = r & 7, rhi = (r >> 3) & 1;
        int ks = d0 >> 3, dhi = (d0 >> 2) & 1;
        int reg = dhi * 2 + rhi;
        uint32_t vals[4] = {f2t(qv.x), f2t(qv.y), f2t(qv.z), f2t(qv.w)};
        #pragma unroll
        for (int e = 0; e < 4; e++) {
            int L = gg * 4 + e;
            QS[wt * 1024 + L * 32 + ((ks ^ (L & 7)) << 2) + reg] = vals[e];
        }
    }

    float Oa[8][4];
    #pragma unroll
    for (int i = 0; i < 8; i++)
        #pragma unroll
        for (int j = 0; j < 4; j++) Oa[i][j] = 0.0f;
    float rs0 = 0.0f, rs1 = 0.0f;

    const unsigned long long* mb0p = (const unsigned long long*)g_maskbits
                                   + (size_t)(n * QL + q0 + w * 16 + g) * 32;
    const unsigned long long* mb1p = mb0p + 8 * 32;

    uint32_t* pw = PS + w * 1088 + g * 136;

    for (int ch = 0; ch < NCHUNK; ch++) {
        const int k0 = ch * BN;
        __syncthreads();   /* previous chunk's PV done reading KS/VS */

        unsigned long long m0 = mb0p[ch];
        unsigned long long m1 = mb1p[ch];

        /* ---- stage K/V fragments for this chunk */
        #pragma unroll
        for (int j = 0; j < 4; j++) {
            int flat = tid + 256 * j;
            int r = flat >> 4, d0 = (flat & 15) * 4;
            float4 kv4 = *(const float4*)(kb + (size_t)(k0 + r) * ED + d0);
            float4 vv4 = *(const float4*)(vb + (size_t)(k0 + r) * ED + d0);
            {   /* K: tile ns=r>>3, owner g=r&7; k-dims: ks=d0>>3, hi=(d0>>2)&1 */
                int ns = r >> 3, gg = r & 7, ks = d0 >> 3, hi = (d0 >> 2) & 1;
                int pre = ((ks & 1) << 1) + hi, ksg = ks >> 1;
                uint32_t vals[4] = {f2t(kv4.x), f2t(kv4.y), f2t(kv4.z), f2t(kv4.w)};
                #pragma unroll
                for (int e = 0; e < 4; e++) {
                    int L = gg * 4 + e;
                    KS[((ns * 32 + L) << 4) + ((ksg ^ ((L >> 1) & 3)) << 2) + pre]
                        = vals[e];
                }
            }
            {   /* V: tile ds=d0>>3, owner g=d&7; k-dims from kvrow r */
                int cf = r & 3, ks = r >> 3, hi = (r >> 2) & 1, ds = d0 >> 3;
                int g0 = d0 & 7;
                int pre = ((ks & 1) << 1) + hi, ksg = ks >> 1;
                uint32_t vals[4] = {f2t(vv4.x), f2t(vv4.y), f2t(vv4.z), f2t(vv4.w)};
                #pragma unroll
                for (int e = 0; e < 4; e++) {
                    int L = (g0 + e) * 4 + cf;
                    VS[((ds * 32 + L) << 4) + ((ksg ^ ((L >> 1) & 3)) << 2) + pre]
                        = vals[e];
                }
            }
        }
        __syncthreads();

        /* ---- load Q A-fragments (per chunk: frees regs for aP in PV phase) */
        uint32_t aQ[8][4];
        {
            const uint32_t* qwp = QS + w * 1024 + Lme * 32;
            #pragma unroll
            for (int ks = 0; ks < 8; ks++) {
                uint4 t = *(const uint4*)(qwp + ((ks ^ (Lme & 7)) << 2));
                aQ[ks][0] = t.x; aQ[ks][1] = t.y;
                aQ[ks][2] = t.z; aQ[ks][3] = t.w;
            }
        }

        /* ---- S = Q K^T */
        float S[8][4];
        #pragma unroll
        for (int i = 0; i < 8; i++)
            #pragma unroll
            for (int j = 0; j < 4; j++) S[i][j] = 0.0f;
        #pragma unroll
        for (int ns = 0; ns < 8; ns++) {
            const uint32_t* kbp = KS + ((ns * 32 + Lme) << 4);
            #pragma unroll
            for (int kg = 0; kg < 4; kg++) {
                uint4 bb = *(const uint4*)(kbp + ((kg ^ xL) << 2));
                mma8(S[ns], aQ[2 * kg],     bb.x, bb.y);
                mma8(S[ns], aQ[2 * kg + 1], bb.z, bb.w);
            }
        }

        /* ---- softmax (no max-sub): p = bit ? exp2(s*K2E) : 0, tf32-rounded.
           Store P fragments: word = g*136 + ns*16 + 4c (+rp/col packing). */
        #pragma unroll
        for (int ns = 0; ns < 8; ns++) {
            int sh = ns * 8 + 2 * c;
            uint32_t bm0 = (uint32_t)(m0 >> sh);
            uint32_t bm1 = (uint32_t)(m1 >> sh);
            float e0 = (bm0 & 1u) ? ex2f(S[ns][0] * K2E) : 0.0f;
            float e1 = (bm0 & 2u) ? ex2f(S[ns][1] * K2E) : 0.0f;
            float e2 = (bm1 & 1u) ? ex2f(S[ns][2] * K2E) : 0.0f;
            float e3 = (bm1 & 2u) ? ex2f(S[ns][3] * K2E) : 0.0f;
            uint32_t h0 = f2t(e0), h1 = f2t(e1), h2 = f2t(e2), h3 = f2t(e3);
            rs0 += __uint_as_float(h0) + __uint_as_float(h1);
            rs1 += __uint_as_float(h2) + __uint_as_float(h3);
            *(uint4*)(pw + ns * 16 + 4 * c) = make_uint4(h0, h2, h1, h3);
        }
        __syncwarp();

        /* ---- load P A-fragments (LDS.64, conflict-free) */
        uint32_t aP[8][4];
        #pragma unroll
        for (int ks = 0; ks < 8; ks++) {
            uint2 lo = *(const uint2*)(pw + ks * 16 + 2 * c);
            uint2 hi = *(const uint2*)(pw + ks * 16 + 2 * (c + 4));
            aP[ks][0] = lo.x; aP[ks][1] = lo.y;
            aP[ks][2] = hi.x; aP[ks][3] = hi.y;
        }

        /* ---- O += P V */
        #pragma unroll
        for (int ds = 0; ds < 8; ds++) {
            const uint32_t* vbp = VS + ((ds * 32 + Lme) << 4);
            #pragma unroll
            for (int kg = 0; kg < 4; kg++) {
                uint4 bb = *(const uint4*)(vbp + ((kg ^ xL) << 2));
                mma8(Oa[ds], aP[2 * kg],     bb.x, bb.y);
                mma8(Oa[ds], aP[2 * kg + 1], bb.z, bb.w);
            }
        }
    }

    /* row-sum reduce across quad, normalize, write */
    rs0 += __shfl_xor_sync(0xffffffffu, rs0, 1);
    rs0 += __shfl_xor_sync(0xffffffffu, rs0, 2);
    rs1 += __shfl_xor_sync(0xffffffffu, rs1, 1);
    rs1 += __shfl_xor_sync(0xffffffffu, rs1, 2);
    float inv0 = 1.0f / rs0, inv1 = 1.0f / rs1;

    float* ob0 = g_attn + (size_t)(n * QL + q0 + w * 16 + g) * ED + h * HD;
    float* ob1 = ob0 + (size_t)8 * ED;
    #pragma unroll
    for (int ds = 0; ds < 8; ds++) {
        *(float2*)(ob0 + ds * 8 + 2 * c) =
            make_float2(Oa[ds][0] * inv0, Oa[ds][1] * inv0);
        *(float2*)(ob1 + ds * 8 + 2 * c) =
            make_float2(Oa[ds][2] * inv1, Oa[ds][3] * inv1);
    }
}

/* ------------- projection Y = X W^T + b (tf32 mma, plain X) -------------- */
#define PP 36   /* pitch words, PP%32==4 */

__global__ __launch_bounds__(256, 2)
void proj_mma(const float* __restrict__ W, const float* __restrict__ bias,
              float* __restrict__ Y)
{
    extern __shared__ uint32_t ps[];
    uint32_t* XH = ps;                  /* [128][36] */
    uint32_t* WS = ps + 128 * PP;

    const int tid = threadIdx.x, w = tid >> 5, lane = tid & 31;
    const int g = lane >> 2, c = lane & 3;
    const int wm = w & 3, wn = w >> 2;
    const int m0 = blockIdx.y * 128, n0 = blockIdx.x * 128;
    const float* X = g_attn;

    float D[2][8][4];
    #pragma unroll
    for (int a = 0; a < 2; a++)
        #pragma unroll
        for (int i = 0; i < 8; i++)
            #pragma unroll
            for (int j = 0; j < 4; j++) D[a][i][j] = 0.0f;

    for (int kt = 0; kt < 32; kt++) {
        const int k0 = kt * 32;
        __syncthreads();
        #pragma unroll
        for (int j = 0; j < 4; j++) {
            int flat = tid + 256 * j, r = flat >> 3, c4 = flat & 7;
            float4 xv = *(const float4*)(X + (size_t)(m0 + r) * ED + k0 + c4 * 4);
            uint32_t* dh = XH + r * PP + c4 * 4;
            dh[0] = f2t(xv.x); dh[1] = f2t(xv.y);
            dh[2] = f2t(xv.z); dh[3] = f2t(xv.w);
            float4 wv = *(const float4*)(W + (size_t)(n0 + r) * ED + k0 + c4 * 4);
            uint32_t* dw = WS + r * PP + c4 * 4;
            dw[0] = f2t(wv.x); dw[1] = f2t(wv.y);
            dw[2] = f2t(wv.z); dw[3] = f2t(wv.w);
        }
        __syncthreads();

        #pragma unroll
        for (int ks = 0; ks < 4; ks++) {
            uint32_t A[2][4];
            #pragma unroll
            for (int mi = 0; mi < 2; mi++) {
                int rb = wm * 32 + mi * 16;
                const uint32_t* p0 = XH + (rb + g) * PP + ks * 8 + c;
                const uint32_t* p1 = XH + (rb + g + 8) * PP + ks * 8 + c;
                A[mi][0] = p0[0]; A[mi][2] = p0[4];
                A[mi][1] = p1[0]; A[mi][3] = p1[4];
            }
            #pragma unroll
            for (int ns = 0; ns < 8; ns++) {
                const uint32_t* bp = WS + (wn * 64 + ns * 8 + g) * PP + ks * 8 + c;
                uint32_t b0 = bp[0], b1 = bp[4];
                mma8(D[0][ns], A[0], b0, b1);
                mma8(D[1][ns], A[1], b0, b1);
            }
        }
    }

    #pragma unroll
    for (int mi = 0; mi < 2; mi++) {
        int row0 = m0 + wm * 32 + mi * 16 + g;
        #pragma unroll
        for (int ns = 0; ns < 8; ns++) {
            int col = n0 + wn * 64 + ns * 8 + 2 * c;
            float2 bv = *(const float2*)(bias + col);
            *(float2*)(Y + (size_t)row0 * ED + col) =
                make_float2(D[mi][ns][0] + bv.x, D[mi][ns][1] + bv.y);
            *(float2*)(Y + (size_t)(row0 + 8) * ED + col) =
                make_float2(D[mi][ns][2] + bv.x, D[mi][ns][3] + bv.y);
        }
    }
}

/* --------------------------------- launch -------------------------------- */
extern "C" void kernel_launch(void* const* d_in, const int* in_sizes, int n_in,
                              void* d_out, int out_size)
{
    const float* q    = (const float*)d_in[0];
    const float* k    = (const float*)d_in[1];
    const float* v    = (const float*)d_in[2];
    const int*   mask = (const int*)  d_in[3];
    const float* W    = (const float*)d_in[4];
    const float* b    = (const float*)d_in[5];
    float* out = (float*)d_out;

    const int smem_proj = 2 * 128 * PP * 4;             /* 36864 */
    cudaFuncSetAttribute(attn_mma, cudaFuncAttributeMaxDynamicSharedMemorySize, SMEM_BYTES);
    cudaFuncSetAttribute(proj_mma, cudaFuncAttributeMaxDynamicSharedMemorySize, smem_proj);

    maskpack<<<8192, 256>>>(mask);

    dim3 g1(QL / BQ, NBATCH * HEADS);
    attn_mma<<<g1, 256, SMEM_BYTES>>>(q, k, v);

    dim3 g2(ED / 128, (NBATCH * QL) / 128);
    proj_mma<<<g2, 256, smem_proj>>>(W, b, out);
}

// round 6
// speedup vs baseline: 1.1650x; 1.1650x over previous
#include <cuda_runtime.h>
#include <cstdint>

#define NBATCH 4
#define HEADS  16
#define QL     2048
#define KVL    2048
#define HD     64
#define ED     1024
#define K2E    0.045084220027780106f   /* (1/sqrt(1024)) * log2(e) */

#define BQ 256
#define BN 64
#define NCHUNK (KVL / BN)
#define PITCH 68          /* smem pitch (words): %32==4 -> conflict-free frags */

/* scratch: attention output [N, Q, E] fp32 (32 MB) + bit-packed mask (2 MB) */
static __device__ float    g_attn[NBATCH * QL * ED];
static __device__ uint32_t g_maskbits[NBATCH * QL * (KVL / 32)];

/* ----------------------------- small helpers ----------------------------- */
__device__ __forceinline__ uint32_t f2t(float x) {          /* f32 -> tf32 bits */
    uint32_t u;
    asm("cvt.rna.tf32.f32 %0, %1;" : "=r"(u) : "f"(x));
    return u;
}
__device__ __forceinline__ float ex2f(float x) {
    float r;
    asm("ex2.approx.f32 %0, %1;" : "=f"(r) : "f"(x));
    return r;
}

/* D(16x8,f32) += A(16x8,tf32) * B(8x8,tf32)  —  m16n8k8 row.col */
__device__ __forceinline__ void mma8(float* d, const uint32_t* a,
                                     uint32_t b0, uint32_t b1) {
    asm volatile(
        "mma.sync.aligned.m16n8k8.row.col.f32.tf32.tf32.f32 "
        "{%0,%1,%2,%3}, {%4,%5,%6,%7}, {%8,%9}, {%0,%1,%2,%3};"
        : "+f"(d[0]), "+f"(d[1]), "+f"(d[2]), "+f"(d[3])
        : "r"(a[0]), "r"(a[1]), "r"(a[2]), "r"(a[3]), "r"(b0), "r"(b1));
}

/* --------------------------- mask bit-packing ---------------------------- */
__global__ void maskpack(const int* __restrict__ M) {
    int warpid = (blockIdx.x * blockDim.x + threadIdx.x) >> 5;
    int lane = threadIdx.x & 31;
    size_t base = (size_t)warpid * 8;
    #pragma unroll
    for (int t = 0; t < 8; t++) {
        size_t wd = base + t;
        int v = M[wd * 32 + lane];
        uint32_t bits = __ballot_sync(0xffffffffu, v != 0);
        if (lane == 0) g_maskbits[wd] = bits;
    }
}

/* -------------------- tf32 mma.sync flash attention ---------------------- */
/* BQ=256, 8 warps; warp w owns q-rows [w*32, w*32+32) = 2 m16 tiles (mi=0,1).
   K/V B-fragments are loaded once per warp and shared across both tiles:
   halves smem bytes per MAC vs M=16. Softmax fused per ns-tile keeps S regs
   at 8. PV is ks-outer so only the current P A-frags are live.              */
__global__ __launch_bounds__(256, 1)
void attn_mma(const float* __restrict__ Q, const float* __restrict__ K,
              const float* __restrict__ V)
{
    extern __shared__ uint32_t sm[];
    uint32_t* KS = sm;                      /* [64][68]  K chunk (tf32)   */
    uint32_t* VS = sm + 64 * PITCH;         /* [64][68]  V chunk (tf32)   */
    uint32_t* PH = sm + 2 * 64 * PITCH;     /* [256][68] Q staging, then P */

    const int tid = threadIdx.x, w = tid >> 5, lane = tid & 31;
    const int g = lane >> 2, c = lane & 3;
    const int n = blockIdx.y >> 4, h = blockIdx.y & 15;
    const int q0 = blockIdx.x * BQ;

    const float* qb = Q + ((size_t)n * QL + q0) * ED + h * HD;
    const float* kb = K + (size_t)n * KVL * ED + h * HD;
    const float* vb = V + (size_t)n * KVL * ED + h * HD;

    /* ---- stage Q (tf32) into PH [256][68] */
    #pragma unroll
    for (int j = 0; j < 16; j++) {
        int flat = tid + 256 * j, r = flat >> 4, d0 = (flat & 15) * 4;
        float4 v = *(const float4*)(qb + (size_t)r * ED + d0);
        uint32_t* d = PH + r * PITCH + d0;
        d[0] = f2t(v.x); d[1] = f2t(v.y); d[2] = f2t(v.z); d[3] = f2t(v.w);
    }
    __syncthreads();

    /* ---- resident Q A-fragments: 2 tiles x 8 ks x 4 regs */
    uint32_t aQ[2][8][4];
    #pragma unroll
    for (int mi = 0; mi < 2; mi++) {
        int rb = w * 32 + mi * 16;
        #pragma unroll
        for (int ks = 0; ks < 8; ks++) {
            const uint32_t* p0 = PH + (rb + g) * PITCH + ks * 8 + c;
            const uint32_t* p1 = p0 + 8 * PITCH;
            aQ[mi][ks][0] = p0[0]; aQ[mi][ks][2] = p0[4];
            aQ[mi][ks][1] = p1[0]; aQ[mi][ks][3] = p1[4];
        }
    }

    float Oa[2][8][4];
    #pragma unroll
    for (int mi = 0; mi < 2; mi++)
        #pragma unroll
        for (int i = 0; i < 8; i++)
            #pragma unroll
            for (int j = 0; j < 4; j++) Oa[mi][i][j] = 0.0f;
    float rs00 = 0.0f, rs01 = 0.0f, rs10 = 0.0f, rs11 = 0.0f;

    /* bit-mask row pointers: [mi][row-half], 1 ull = 64 kv bits per chunk */
    const unsigned long long* mbase = (const unsigned long long*)g_maskbits;
    const unsigned long long* mp00 = mbase + (size_t)(n * QL + q0 + w * 32 + g) * 32;
    const unsigned long long* mp01 = mp00 + 8 * 32;
    const unsigned long long* mp10 = mp00 + 16 * 32;
    const unsigned long long* mp11 = mp00 + 24 * 32;

    uint32_t* PW = PH + w * 32 * PITCH;    /* per-warp private P buffer */

    /* ---- prefetch chunk 0 into registers */
    float4 pk[4], pv[4];
    #pragma unroll
    for (int j = 0; j < 4; j++) {
        int flat = tid + 256 * j, r = flat >> 4, d0 = (flat & 15) * 4;
        pk[j] = *(const float4*)(kb + (size_t)r * ED + d0);
        pv[j] = *(const float4*)(vb + (size_t)r * ED + d0);
    }

    for (int ch = 0; ch < NCHUNK; ch++) {
        __syncthreads();   /* previous chunk's PV done reading KS/VS */
        #pragma unroll
        for (int j = 0; j < 4; j++) {
            int flat = tid + 256 * j, r = flat >> 4, d0 = (flat & 15) * 4;
            uint32_t* dk = KS + r * PITCH + d0;
            dk[0] = f2t(pk[j].x); dk[1] = f2t(pk[j].y);
            dk[2] = f2t(pk[j].z); dk[3] = f2t(pk[j].w);
            uint32_t* dv = VS + r * PITCH + d0;
            dv[0] = f2t(pv[j].x); dv[1] = f2t(pv[j].y);
            dv[2] = f2t(pv[j].z); dv[3] = f2t(pv[j].w);
        }
        if (ch + 1 < NCHUNK) {
            const float* kn = kb + (size_t)(ch + 1) * BN * ED;
            const float* vn = vb + (size_t)(ch + 1) * BN * ED;
            #pragma unroll
            for (int j = 0; j < 4; j++) {
                int flat = tid + 256 * j, r = flat >> 4, d0 = (flat & 15) * 4;
                pk[j] = *(const float4*)(kn + (size_t)r * ED + d0);
                pv[j] = *(const float4*)(vn + (size_t)r * ED + d0);
            }
        }
        __syncthreads();

        unsigned long long m00 = mp00[ch], m01 = mp01[ch];
        unsigned long long m10 = mp10[ch], m11 = mp11[ch];

        /* ---- QK + fused softmax, one ns-tile (8 cols) at a time */
        #pragma unroll
        for (int ns = 0; ns < 8; ns++) {
            float S0[4] = {0.f, 0.f, 0.f, 0.f};
            float S1[4] = {0.f, 0.f, 0.f, 0.f};
            #pragma unroll
            for (int ks = 0; ks < 8; ks++) {
                const uint32_t* bp = KS + (ns * 8 + g) * PITCH + ks * 8 + c;
                uint32_t b0 = bp[0], b1 = bp[4];
                mma8(S0, aQ[0][ks], b0, b1);
                mma8(S1, aQ[1][ks], b0, b1);
            }
            int sh = ns * 8 + 2 * c;
            {   /* tile mi = 0 */
                uint32_t bm0 = (uint32_t)(m00 >> sh);
                uint32_t bm1 = (uint32_t)(m01 >> sh);
                float e0 = (bm0 & 1u) ? ex2f(S0[0] * K2E) : 0.0f;
                float e1 = (bm0 & 2u) ? ex2f(S0[1] * K2E) : 0.0f;
                float e2 = (bm1 & 1u) ? ex2f(S0[2] * K2E) : 0.0f;
                float e3 = (bm1 & 2u) ? ex2f(S0[3] * K2E) : 0.0f;
                uint32_t h0 = f2t(e0), h1 = f2t(e1), h2 = f2t(e2), h3 = f2t(e3);
                rs00 += __uint_as_float(h0) + __uint_as_float(h1);
                rs01 += __uint_as_float(h2) + __uint_as_float(h3);
                uint32_t* d0 = PW + g * PITCH + ns * 8 + 2 * c;
                uint32_t* d1 = d0 + 8 * PITCH;
                d0[0] = h0; d0[1] = h1; d1[0] = h2; d1[1] = h3;
            }
            {   /* tile mi = 1 */
                uint32_t bm0 = (uint32_t)(m10 >> sh);
                uint32_t bm1 = (uint32_t)(m11 >> sh);
                float e0 = (bm0 & 1u) ? ex2f(S1[0] * K2E) : 0.0f;
                float e1 = (bm0 & 2u) ? ex2f(S1[1] * K2E) : 0.0f;
                float e2 = (bm1 & 1u) ? ex2f(S1[2] * K2E) : 0.0f;
                float e3 = (bm1 & 2u) ? ex2f(S1[3] * K2E) : 0.0f;
                uint32_t h0 = f2t(e0), h1 = f2t(e1), h2 = f2t(e2), h3 = f2t(e3);
                rs10 += __uint_as_float(h0) + __uint_as_float(h1);
                rs11 += __uint_as_float(h2) + __uint_as_float(h3);
                uint32_t* d0 = PW + (16 + g) * PITCH + ns * 8 + 2 * c;
                uint32_t* d1 = d0 + 8 * PITCH;
                d0[0] = h0; d0[1] = h1; d1[0] = h2; d1[1] = h3;
            }
        }
        __syncwarp();

        /* ---- O += P V : ks-outer so only current P A-frags are live */
        #pragma unroll
        for (int ks = 0; ks < 8; ks++) {
            uint32_t aP0[4], aP1[4];
            {
                const uint32_t* p0 = PW + g * PITCH + ks * 8 + c;
                const uint32_t* p1 = p0 + 8 * PITCH;
                aP0[0] = p0[0]; aP0[2] = p0[4];
                aP0[1] = p1[0]; aP0[3] = p1[4];
                const uint32_t* r0p = PW + (16 + g) * PITCH + ks * 8 + c;
                const uint32_t* r1p = r0p + 8 * PITCH;
                aP1[0] = r0p[0]; aP1[2] = r0p[4];
                aP1[1] = r1p[0]; aP1[3] = r1p[4];
            }
            #pragma unroll
            for (int ds = 0; ds < 8; ds++) {
                uint32_t b0 = VS[(ks * 8 + c) * PITCH + ds * 8 + g];
                uint32_t b1 = VS[(ks * 8 + c + 4) * PITCH + ds * 8 + g];
                mma8(Oa[0][ds], aP0, b0, b1);
                mma8(Oa[1][ds], aP1, b0, b1);
            }
        }
    }

    /* row-sum reduce across quad, normalize, write */
    rs00 += __shfl_xor_sync(0xffffffffu, rs00, 1);
    rs00 += __shfl_xor_sync(0xffffffffu, rs00, 2);
    rs01 += __shfl_xor_sync(0xffffffffu, rs01, 1);
    rs01 += __shfl_xor_sync(0xffffffffu, rs01, 2);
    rs10 += __shfl_xor_sync(0xffffffffu, rs10, 1);
    rs10 += __shfl_xor_sync(0xffffffffu, rs10, 2);
    rs11 += __shfl_xor_sync(0xffffffffu, rs11, 1);
    rs11 += __shfl_xor_sync(0xffffffffu, rs11, 2);

    #pragma unroll
    for (int mi = 0; mi < 2; mi++) {
        float inv0 = 1.0f / (mi ? rs10 : rs00);
        float inv1 = 1.0f / (mi ? rs11 : rs01);
        float* ob0 = g_attn
            + (size_t)(n * QL + q0 + w * 32 + mi * 16 + g) * ED + h * HD;
        float* ob1 = ob0 + (size_t)8 * ED;
        #pragma unroll
        for (int ds = 0; ds < 8; ds++) {
            *(float2*)(ob0 + ds * 8 + 2 * c) =
                make_float2(Oa[mi][ds][0] * inv0, Oa[mi][ds][1] * inv0);
            *(float2*)(ob1 + ds * 8 + 2 * c) =
                make_float2(Oa[mi][ds][2] * inv1, Oa[mi][ds][3] * inv1);
        }
    }
}

/* ------------- projection Y = X W^T + b (tf32 mma, plain X) -------------- */
#define PP 36   /* pitch words, PP%32==4 */

__global__ __launch_bounds__(256, 2)
void proj_mma(const float* __restrict__ W, const float* __restrict__ bias,
              float* __restrict__ Y)
{
    extern __shared__ uint32_t ps[];
    uint32_t* XH = ps;                  /* [128][36] */
    uint32_t* WS = ps + 128 * PP;

    const int tid = threadIdx.x, w = tid >> 5, lane = tid & 31;
    const int g = lane >> 2, c = lane & 3;
    const int wm = w & 3, wn = w >> 2;
    const int m0 = blockIdx.y * 128, n0 = blockIdx.x * 128;
    const float* X = g_attn;

    float D[2][8][4];
    #pragma unroll
    for (int a = 0; a < 2; a++)
        #pragma unroll
        for (int i = 0; i < 8; i++)
            #pragma unroll
            for (int j = 0; j < 4; j++) D[a][i][j] = 0.0f;

    for (int kt = 0; kt < 32; kt++) {
        const int k0 = kt * 32;
        __syncthreads();
        #pragma unroll
        for (int j = 0; j < 4; j++) {
            int flat = tid + 256 * j, r = flat >> 3, c4 = flat & 7;
            float4 xv = *(const float4*)(X + (size_t)(m0 + r) * ED + k0 + c4 * 4);
            uint32_t* dh = XH + r * PP + c4 * 4;
            dh[0] = f2t(xv.x); dh[1] = f2t(xv.y);
            dh[2] = f2t(xv.z); dh[3] = f2t(xv.w);
            float4 wv = *(const float4*)(W + (size_t)(n0 + r) * ED + k0 + c4 * 4);
            uint32_t* dw = WS + r * PP + c4 * 4;
            dw[0] = f2t(wv.x); dw[1] = f2t(wv.y);
            dw[2] = f2t(wv.z); dw[3] = f2t(wv.w);
        }
        __syncthreads();

        #pragma unroll
        for (int ks = 0; ks < 4; ks++) {
            uint32_t A[2][4];
            #pragma unroll
            for (int mi = 0; mi < 2; mi++) {
                int rb = wm * 32 + mi * 16;
                const uint32_t* p0 = XH + (rb + g) * PP + ks * 8 + c;
                const uint32_t* p1 = XH + (rb + g + 8) * PP + ks * 8 + c;
                A[mi][0] = p0[0]; A[mi][2] = p0[4];
                A[mi][1] = p1[0]; A[mi][3] = p1[4];
            }
            #pragma unroll
            for (int ns = 0; ns < 8; ns++) {
                const uint32_t* bp = WS + (wn * 64 + ns * 8 + g) * PP + ks * 8 + c;
                uint32_t b0 = bp[0], b1 = bp[4];
                mma8(D[0][ns], A[0], b0, b1);
                mma8(D[1][ns], A[1], b0, b1);
            }
        }
    }

    #pragma unroll
    for (int mi = 0; mi < 2; mi++) {
        int row0 = m0 + wm * 32 + mi * 16 + g;
        #pragma unroll
        for (int ns = 0; ns < 8; ns++) {
            int col = n0 + wn * 64 + ns * 8 + 2 * c;
            float2 bv = *(const float2*)(bias + col);
            *(float2*)(Y + (size_t)row0 * ED + col) =
                make_float2(D[mi][ns][0] + bv.x, D[mi][ns][1] + bv.y);
            *(float2*)(Y + (size_t)(row0 + 8) * ED + col) =
                make_float2(D[mi][ns][2] + bv.x, D[mi][ns][3] + bv.y);
        }
    }
}

/* --------------------------------- launch -------------------------------- */
extern "C" void kernel_launch(void* const* d_in, const int* in_sizes, int n_in,
                              void* d_out, int out_size)
{
    const float* q    = (const float*)d_in[0];
    const float* k    = (const float*)d_in[1];
    const float* v    = (const float*)d_in[2];
    const int*   mask = (const int*)  d_in[3];
    const float* W    = (const float*)d_in[4];
    const float* b    = (const float*)d_in[5];
    float* out = (float*)d_out;

    const int smem_attn = (2 * 64 + 256) * PITCH * 4;   /* 104448 */
    const int smem_proj = 2 * 128 * PP * 4;             /* 36864  */
    cudaFuncSetAttribute(attn_mma, cudaFuncAttributeMaxDynamicSharedMemorySize, smem_attn);
    cudaFuncSetAttribute(proj_mma, cudaFuncAttributeMaxDynamicSharedMemorySize, smem_proj);

    maskpack<<<8192, 256>>>(mask);

    dim3 g1(QL / BQ, NBATCH * HEADS);
    attn_mma<<<g1, 256, smem_attn>>>(q, k, v);

    dim3 g2(ED / 128, (NBATCH * QL) / 128);
    proj_mma<<<g2, 256, smem_proj>>>(W, b, out);
}